// round 11
// baseline (speedup 1.0000x reference)
#include <cuda_runtime.h>
#include <cuda_bf16.h>

// DensityEstimator: per-channel 1->3->3->3->1 MLP, p = cdf(x+.5) - cdf(x-.5)
// R11: R10 unchanged except the residency fix. At 256-thr/64-reg the 4th
// block/SM never fit (64*1024 = exact RF size + granularity) -> only 24
// resident warps (achieved occ 35.7% across all clean rounds). 192-thread
// blocks at __launch_bounds__(192,5): 30 warps x 2048-reg chunks = 61440 regs
// fits -> 30 resident warps at the SAME 64-reg budget, no spills.
// blockDim=192 also makes c = threadIdx.x exactly (every block channel-aligned).
// Grid 740 = 5 x 148 SMs -> perfect single wave.

#define NCH  192
#define NBLK 740
#define NTHR 192
#define NW   43

__device__ float g_wt[NW * NCH];   // transformed weights, [k][c]

__device__ __forceinline__ float tanha(float x) {
    float r; asm("tanh.approx.f32 %0, %1;" : "=f"(r) : "f"(x)); return r;
}
__device__ __forceinline__ float softplus_acc(float h) {
    return (h > 15.0f) ? h : log1pf(expf(h));
}

// ---- Kernel 1: data-parallel weight transform, one thread per weight ----
// k: 0-2 sh0 | 3-5 bp0 | 6-8 ta0 | 9-17 sh1 | 18-20 ta1 | 21-23 bb1
//    24-32 sh2 | 33-35 ta2 | 36-38 bb2 | 39-41 sh3(1/2) | 42 bb3(1/2)
__global__ void wt_kernel(
    const float* __restrict__ a0, const float* __restrict__ a1, const float* __restrict__ a2,
    const float* __restrict__ b0, const float* __restrict__ b1, const float* __restrict__ b2,
    const float* __restrict__ b3,
    const float* __restrict__ H0, const float* __restrict__ H1, const float* __restrict__ H2,
    const float* __restrict__ H3)
{
    int t = blockIdx.x * blockDim.x + threadIdx.x;
    if (t >= NW * NCH) return;
    int k = t / NCH;
    int c = t % NCH;
    float v;
    if      (k <  3) v = softplus_acc(H0[c*3 + k]);
    else if (k <  6) { int j = k - 3;
                       v = fmaf(0.5f, softplus_acc(H0[c*3 + j]), b0[c*3 + j]); }
    else if (k <  9) v = tanhf(a0[c*3 + (k - 6)]);
    else if (k < 18) v = softplus_acc(H1[c*9 + (k - 9)]);
    else if (k < 21) v = tanhf(a1[c*3 + (k - 18)]);
    else if (k < 24) v = b1[c*3 + (k - 21)];
    else if (k < 33) v = softplus_acc(H2[c*9 + (k - 24)]);
    else if (k < 36) v = tanhf(a2[c*3 + (k - 33)]);
    else if (k < 39) v = b2[c*3 + (k - 36)];
    else if (k < 42) v = 0.5f * softplus_acc(H3[c*3 + (k - 39)]);
    else             v = 0.5f * b3[c];
    g_wt[k * NCH + c] = v;
}

// ---- One element, both cdf branches (tm = tp - sh0[j], exact) ----
struct W {
    float sh0[3], bp0[3], ta0[3], sh1[9], ta1[3], bb1[3];
    float sh2[9], ta2[3], bb2[3], sh3[3], bb3;
};

__device__ __forceinline__ float de_one(float xv, const W& w) {
    float yp[3], ym[3];
#pragma unroll
    for (int j = 0; j < 3; j++) {
        float tp = fmaf(xv, w.sh0[j], w.bp0[j]);   // at x + 0.5
        float tm = tp - w.sh0[j];                  // at x - 0.5
        yp[j] = fmaf(w.ta0[j], tanha(tp), tp);
        ym[j] = fmaf(w.ta0[j], tanha(tm), tm);
    }
    float zp[3], zm[3];
#pragma unroll
    for (int p = 0; p < 3; p++) {
        float sp = w.bb1[p], sm = w.bb1[p];
#pragma unroll
        for (int j = 0; j < 3; j++) {
            sp = fmaf(yp[j], w.sh1[j*3 + p], sp);
            sm = fmaf(ym[j], w.sh1[j*3 + p], sm);
        }
        zp[p] = fmaf(w.ta1[p], tanha(sp), sp);
        zm[p] = fmaf(w.ta1[p], tanha(sm), sm);
    }
#pragma unroll
    for (int p = 0; p < 3; p++) {
        float sp = w.bb2[p], sm = w.bb2[p];
#pragma unroll
        for (int j = 0; j < 3; j++) {
            sp = fmaf(zp[j], w.sh2[j*3 + p], sp);
            sm = fmaf(zm[j], w.sh2[j*3 + p], sm);
        }
        yp[p] = fmaf(w.ta2[p], tanha(sp), sp);
        ym[p] = fmaf(w.ta2[p], tanha(sm), sm);
    }
    float fp = w.bb3, fm = w.bb3;
#pragma unroll
    for (int j = 0; j < 3; j++) {
        fp = fmaf(yp[j], w.sh3[j], fp);
        fm = fmaf(ym[j], w.sh3[j], fm);
    }
    return 0.5f * (tanha(fp) - tanha(fm));
}

// ---- Kernel 2: main evaluation, 30 resident warps/SM ----
__global__ void __launch_bounds__(NTHR, 5) de_kernel(
    const float* __restrict__ x, float* __restrict__ out, int n)
{
    const int T  = gridDim.x * blockDim.x;          // 142080, multiple of 192
    const int i0 = blockIdx.x * blockDim.x + threadIdx.x;
    const int c  = threadIdx.x;                     // blockDim == 192 == NCH

    // 43 coalesced loads (lane-consecutive c), laundered via identity shfl.
    W w;
    float* wf = (float*)&w;
#pragma unroll
    for (int k = 0; k < NW; k++) {
        float v = g_wt[k * NCH + c];
        wf[k] = __shfl_sync(0xffffffffu, v, threadIdx.x & 31);
    }

    for (int i = i0; i < n; i += 2 * T) {
        const int  i2  = i + T;                     // same channel (T % 192 == 0)
        const bool ok2 = i2 < n;
        float xa = x[i];
        float xb = x[ok2 ? i2 : i];
        float ra = de_one(xa, w);
        float rb = de_one(xb, w);
        out[i] = ra;
        if (ok2) out[i2] = rb;
    }
}

extern "C" void kernel_launch(void* const* d_in, const int* in_sizes, int n_in,
                              void* d_out, int out_size)
{
    const float* x  = (const float*)d_in[0];
    const float* a0 = (const float*)d_in[1];
    const float* a1 = (const float*)d_in[2];
    const float* a2 = (const float*)d_in[3];
    const float* b0 = (const float*)d_in[4];
    const float* b1 = (const float*)d_in[5];
    const float* b2 = (const float*)d_in[6];
    const float* b3 = (const float*)d_in[7];
    const float* H0 = (const float*)d_in[8];
    const float* H1 = (const float*)d_in[9];
    const float* H2 = (const float*)d_in[10];
    const float* H3 = (const float*)d_in[11];
    float* out = (float*)d_out;
    int n = in_sizes[0];   // 65536 * 192

    wt_kernel<<<(NW * NCH + 255) / 256, 256>>>(
        a0, a1, a2, b0, b1, b2, b3, H0, H1, H2, H3);
    de_kernel<<<NBLK, NTHR>>>(x, out, n);
}

// round 12
// speedup vs baseline: 1.0251x; 1.0251x over previous
#include <cuda_runtime.h>
#include <cuda_bf16.h>

// DensityEstimator: per-channel 1->3->3->3->1 MLP, p = cdf(x+.5) - cdf(x-.5)
// R12: R10 body unchanged. Residency fix done RIGHT this time: R11's 192-thr
// blocks put 6 warps on SMSPs {2,2,1,1} -> 5 blocks = {10,10,5,5} per SMSP,
// catastrophically unbalanced for the per-SMSP MUFU pipe. 128-thr blocks are
// 1 warp per SMSP; __launch_bounds__(128,7) -> 7 blocks/SM = 7 warps/SMSP,
// perfectly balanced 28 resident warps at the same 64-reg no-spill budget.
// Grid 1035 = 3*345: 1035*128 = 132480 = 192*690 (channel fixed per thread),
// 6.99 blocks/SM -> single wave.

#define NCH  192
#define NBLK 1035
#define NTHR 128
#define NW   43

__device__ float g_wt[NW * NCH];   // transformed weights, [k][c]

__device__ __forceinline__ float tanha(float x) {
    float r; asm("tanh.approx.f32 %0, %1;" : "=f"(r) : "f"(x)); return r;
}
__device__ __forceinline__ float softplus_acc(float h) {
    return (h > 15.0f) ? h : log1pf(expf(h));
}

// ---- Kernel 1: data-parallel weight transform, one thread per weight ----
// k: 0-2 sh0 | 3-5 bp0 | 6-8 ta0 | 9-17 sh1 | 18-20 ta1 | 21-23 bb1
//    24-32 sh2 | 33-35 ta2 | 36-38 bb2 | 39-41 sh3(1/2) | 42 bb3(1/2)
__global__ void wt_kernel(
    const float* __restrict__ a0, const float* __restrict__ a1, const float* __restrict__ a2,
    const float* __restrict__ b0, const float* __restrict__ b1, const float* __restrict__ b2,
    const float* __restrict__ b3,
    const float* __restrict__ H0, const float* __restrict__ H1, const float* __restrict__ H2,
    const float* __restrict__ H3)
{
    int t = blockIdx.x * blockDim.x + threadIdx.x;
    if (t >= NW * NCH) return;
    int k = t / NCH;
    int c = t % NCH;
    float v;
    if      (k <  3) v = softplus_acc(H0[c*3 + k]);
    else if (k <  6) { int j = k - 3;
                       v = fmaf(0.5f, softplus_acc(H0[c*3 + j]), b0[c*3 + j]); }
    else if (k <  9) v = tanhf(a0[c*3 + (k - 6)]);
    else if (k < 18) v = softplus_acc(H1[c*9 + (k - 9)]);
    else if (k < 21) v = tanhf(a1[c*3 + (k - 18)]);
    else if (k < 24) v = b1[c*3 + (k - 21)];
    else if (k < 33) v = softplus_acc(H2[c*9 + (k - 24)]);
    else if (k < 36) v = tanhf(a2[c*3 + (k - 33)]);
    else if (k < 39) v = b2[c*3 + (k - 36)];
    else if (k < 42) v = 0.5f * softplus_acc(H3[c*3 + (k - 39)]);
    else             v = 0.5f * b3[c];
    g_wt[k * NCH + c] = v;
}

// ---- One element, both cdf branches (tm = tp - sh0[j], exact) ----
struct W {
    float sh0[3], bp0[3], ta0[3], sh1[9], ta1[3], bb1[3];
    float sh2[9], ta2[3], bb2[3], sh3[3], bb3;
};

__device__ __forceinline__ float de_one(float xv, const W& w) {
    float yp[3], ym[3];
#pragma unroll
    for (int j = 0; j < 3; j++) {
        float tp = fmaf(xv, w.sh0[j], w.bp0[j]);   // at x + 0.5
        float tm = tp - w.sh0[j];                  // at x - 0.5
        yp[j] = fmaf(w.ta0[j], tanha(tp), tp);
        ym[j] = fmaf(w.ta0[j], tanha(tm), tm);
    }
    float zp[3], zm[3];
#pragma unroll
    for (int p = 0; p < 3; p++) {
        float sp = w.bb1[p], sm = w.bb1[p];
#pragma unroll
        for (int j = 0; j < 3; j++) {
            sp = fmaf(yp[j], w.sh1[j*3 + p], sp);
            sm = fmaf(ym[j], w.sh1[j*3 + p], sm);
        }
        zp[p] = fmaf(w.ta1[p], tanha(sp), sp);
        zm[p] = fmaf(w.ta1[p], tanha(sm), sm);
    }
#pragma unroll
    for (int p = 0; p < 3; p++) {
        float sp = w.bb2[p], sm = w.bb2[p];
#pragma unroll
        for (int j = 0; j < 3; j++) {
            sp = fmaf(zp[j], w.sh2[j*3 + p], sp);
            sm = fmaf(zm[j], w.sh2[j*3 + p], sm);
        }
        yp[p] = fmaf(w.ta2[p], tanha(sp), sp);
        ym[p] = fmaf(w.ta2[p], tanha(sm), sm);
    }
    float fp = w.bb3, fm = w.bb3;
#pragma unroll
    for (int j = 0; j < 3; j++) {
        fp = fmaf(yp[j], w.sh3[j], fp);
        fm = fmaf(ym[j], w.sh3[j], fm);
    }
    return 0.5f * (tanha(fp) - tanha(fm));
}

// ---- Kernel 2: main evaluation, 28 balanced resident warps/SM ----
__global__ void __launch_bounds__(NTHR, 7) de_kernel(
    const float* __restrict__ x, float* __restrict__ out, int n)
{
    const int T  = gridDim.x * blockDim.x;          // 132480, multiple of 192
    const int i0 = blockIdx.x * blockDim.x + threadIdx.x;
    const int c  = i0 % NCH;                        // fixed channel (T % 192 == 0)

    // 43 coalesced loads (lane-consecutive c), laundered via identity shfl.
    W w;
    float* wf = (float*)&w;
#pragma unroll
    for (int k = 0; k < NW; k++) {
        float v = g_wt[k * NCH + c];
        wf[k] = __shfl_sync(0xffffffffu, v, threadIdx.x & 31);
    }

    for (int i = i0; i < n; i += 2 * T) {
        const int  i2  = i + T;                     // same channel
        const bool ok2 = i2 < n;
        float xa = x[i];
        float xb = x[ok2 ? i2 : i];
        float ra = de_one(xa, w);
        float rb = de_one(xb, w);
        out[i] = ra;
        if (ok2) out[i2] = rb;
    }
}

extern "C" void kernel_launch(void* const* d_in, const int* in_sizes, int n_in,
                              void* d_out, int out_size)
{
    const float* x  = (const float*)d_in[0];
    const float* a0 = (const float*)d_in[1];
    const float* a1 = (const float*)d_in[2];
    const float* a2 = (const float*)d_in[3];
    const float* b0 = (const float*)d_in[4];
    const float* b1 = (const float*)d_in[5];
    const float* b2 = (const float*)d_in[6];
    const float* b3 = (const float*)d_in[7];
    const float* H0 = (const float*)d_in[8];
    const float* H1 = (const float*)d_in[9];
    const float* H2 = (const float*)d_in[10];
    const float* H3 = (const float*)d_in[11];
    float* out = (float*)d_out;
    int n = in_sizes[0];   // 65536 * 192

    wt_kernel<<<(NW * NCH + 255) / 256, 256>>>(
        a0, a1, a2, b0, b1, b2, b3, H0, H1, H2, H3);
    de_kernel<<<NBLK, NTHR>>>(x, out, n);
}

// round 13
// speedup vs baseline: 1.0255x; 1.0004x over previous
#include <cuda_runtime.h>
#include <cuda_bf16.h>

// DensityEstimator: per-channel 1->3->3->3->1 MLP, p = cdf(x+.5) - cdf(x-.5)
// R12: R10 body unchanged. Residency fix done RIGHT this time: R11's 192-thr
// blocks put 6 warps on SMSPs {2,2,1,1} -> 5 blocks = {10,10,5,5} per SMSP,
// catastrophically unbalanced for the per-SMSP MUFU pipe. 128-thr blocks are
// 1 warp per SMSP; __launch_bounds__(128,7) -> 7 blocks/SM = 7 warps/SMSP,
// perfectly balanced 28 resident warps at the same 64-reg no-spill budget.
// Grid 1035 = 3*345: 1035*128 = 132480 = 192*690 (channel fixed per thread),
// 6.99 blocks/SM -> single wave.

#define NCH  192
#define NBLK 1035
#define NTHR 128
#define NW   43

__device__ float g_wt[NW * NCH];   // transformed weights, [k][c]

__device__ __forceinline__ float tanha(float x) {
    float r; asm("tanh.approx.f32 %0, %1;" : "=f"(r) : "f"(x)); return r;
}
__device__ __forceinline__ float softplus_acc(float h) {
    return (h > 15.0f) ? h : log1pf(expf(h));
}

// ---- Kernel 1: data-parallel weight transform, one thread per weight ----
// k: 0-2 sh0 | 3-5 bp0 | 6-8 ta0 | 9-17 sh1 | 18-20 ta1 | 21-23 bb1
//    24-32 sh2 | 33-35 ta2 | 36-38 bb2 | 39-41 sh3(1/2) | 42 bb3(1/2)
__global__ void wt_kernel(
    const float* __restrict__ a0, const float* __restrict__ a1, const float* __restrict__ a2,
    const float* __restrict__ b0, const float* __restrict__ b1, const float* __restrict__ b2,
    const float* __restrict__ b3,
    const float* __restrict__ H0, const float* __restrict__ H1, const float* __restrict__ H2,
    const float* __restrict__ H3)
{
    int t = blockIdx.x * blockDim.x + threadIdx.x;
    if (t >= NW * NCH) return;
    int k = t / NCH;
    int c = t % NCH;
    float v;
    if      (k <  3) v = softplus_acc(H0[c*3 + k]);
    else if (k <  6) { int j = k - 3;
                       v = fmaf(0.5f, softplus_acc(H0[c*3 + j]), b0[c*3 + j]); }
    else if (k <  9) v = tanhf(a0[c*3 + (k - 6)]);
    else if (k < 18) v = softplus_acc(H1[c*9 + (k - 9)]);
    else if (k < 21) v = tanhf(a1[c*3 + (k - 18)]);
    else if (k < 24) v = b1[c*3 + (k - 21)];
    else if (k < 33) v = softplus_acc(H2[c*9 + (k - 24)]);
    else if (k < 36) v = tanhf(a2[c*3 + (k - 33)]);
    else if (k < 39) v = b2[c*3 + (k - 36)];
    else if (k < 42) v = 0.5f * softplus_acc(H3[c*3 + (k - 39)]);
    else             v = 0.5f * b3[c];
    g_wt[k * NCH + c] = v;
}

// ---- One element, both cdf branches (tm = tp - sh0[j], exact) ----
struct W {
    float sh0[3], bp0[3], ta0[3], sh1[9], ta1[3], bb1[3];
    float sh2[9], ta2[3], bb2[3], sh3[3], bb3;
};

__device__ __forceinline__ float de_one(float xv, const W& w) {
    float yp[3], ym[3];
#pragma unroll
    for (int j = 0; j < 3; j++) {
        float tp = fmaf(xv, w.sh0[j], w.bp0[j]);   // at x + 0.5
        float tm = tp - w.sh0[j];                  // at x - 0.5
        yp[j] = fmaf(w.ta0[j], tanha(tp), tp);
        ym[j] = fmaf(w.ta0[j], tanha(tm), tm);
    }
    float zp[3], zm[3];
#pragma unroll
    for (int p = 0; p < 3; p++) {
        float sp = w.bb1[p], sm = w.bb1[p];
#pragma unroll
        for (int j = 0; j < 3; j++) {
            sp = fmaf(yp[j], w.sh1[j*3 + p], sp);
            sm = fmaf(ym[j], w.sh1[j*3 + p], sm);
        }
        zp[p] = fmaf(w.ta1[p], tanha(sp), sp);
        zm[p] = fmaf(w.ta1[p], tanha(sm), sm);
    }
#pragma unroll
    for (int p = 0; p < 3; p++) {
        float sp = w.bb2[p], sm = w.bb2[p];
#pragma unroll
        for (int j = 0; j < 3; j++) {
            sp = fmaf(zp[j], w.sh2[j*3 + p], sp);
            sm = fmaf(zm[j], w.sh2[j*3 + p], sm);
        }
        yp[p] = fmaf(w.ta2[p], tanha(sp), sp);
        ym[p] = fmaf(w.ta2[p], tanha(sm), sm);
    }
    float fp = w.bb3, fm = w.bb3;
#pragma unroll
    for (int j = 0; j < 3; j++) {
        fp = fmaf(yp[j], w.sh3[j], fp);
        fm = fmaf(ym[j], w.sh3[j], fm);
    }
    return 0.5f * (tanha(fp) - tanha(fm));
}

// ---- Kernel 2: main evaluation, 28 balanced resident warps/SM ----
__global__ void __launch_bounds__(NTHR, 7) de_kernel(
    const float* __restrict__ x, float* __restrict__ out, int n)
{
    const int T  = gridDim.x * blockDim.x;          // 132480, multiple of 192
    const int i0 = blockIdx.x * blockDim.x + threadIdx.x;
    const int c  = i0 % NCH;                        // fixed channel (T % 192 == 0)

    // 43 coalesced loads (lane-consecutive c), laundered via identity shfl.
    W w;
    float* wf = (float*)&w;
#pragma unroll
    for (int k = 0; k < NW; k++) {
        float v = g_wt[k * NCH + c];
        wf[k] = __shfl_sync(0xffffffffu, v, threadIdx.x & 31);
    }

    for (int i = i0; i < n; i += 2 * T) {
        const int  i2  = i + T;                     // same channel
        const bool ok2 = i2 < n;
        float xa = x[i];
        float xb = x[ok2 ? i2 : i];
        float ra = de_one(xa, w);
        float rb = de_one(xb, w);
        out[i] = ra;
        if (ok2) out[i2] = rb;
    }
}

extern "C" void kernel_launch(void* const* d_in, const int* in_sizes, int n_in,
                              void* d_out, int out_size)
{
    const float* x  = (const float*)d_in[0];
    const float* a0 = (const float*)d_in[1];
    const float* a1 = (const float*)d_in[2];
    const float* a2 = (const float*)d_in[3];
    const float* b0 = (const float*)d_in[4];
    const float* b1 = (const float*)d_in[5];
    const float* b2 = (const float*)d_in[6];
    const float* b3 = (const float*)d_in[7];
    const float* H0 = (const float*)d_in[8];
    const float* H1 = (const float*)d_in[9];
    const float* H2 = (const float*)d_in[10];
    const float* H3 = (const float*)d_in[11];
    float* out = (float*)d_out;
    int n = in_sizes[0];   // 65536 * 192

    wt_kernel<<<(NW * NCH + 255) / 256, 256>>>(
        a0, a1, a2, b0, b1, b2, b3, H0, H1, H2, H3);
    de_kernel<<<NBLK, NTHR>>>(x, out, n);
}